// round 14
// baseline (speedup 1.0000x reference)
#include <cuda_runtime.h>
#include <stdint.h>

// ParallelTransport: out[e, c, :] = R(rho[e]) @ x[row[e], c, :]
// x: (1, N, 32, 2) fp32 ; edge_index: (2, E) int32 ; rho: (E,) fp32
// out: (1, E, 32, 2) fp32
//
// FINAL (= R10, best: 63.6 us). 16 threads per edge, one float4 (2 channels)
// per thread, ITER=4 slots per thread in batched phases:
//   P1: all index/rho loads (L1-broadcast within 16-lane groups)
//   P2: 4 independent float4 gathers (MLP=4; x table is L2-resident, 12.8 MB)
//   P3: rotate + __stcs streaming stores (evict-first keeps the 410 MB write
//       stream from displacing the gather working set in L2)
// 32-bit slot arithmetic throughout (total = E*16 < 2^31).
// Verified neighbors in design space (v8 loads, ITER=6, persistent grid,
// edge-grouped loads, no-L1-alloc, default stores) all regressed.

#define ITER 4
#define TPB  256

__global__ void __launch_bounds__(TPB)
pt_kernel(const float* __restrict__ x,
          const int* __restrict__ row,
          const float* __restrict__ rho,
          float4* __restrict__ out,
          unsigned total /* E * 16 float4 slots, < 2^31 */)
{
    unsigned base = blockIdx.x * (TPB * ITER) + threadIdx.x;

    bool   ok[ITER];
    int    r[ITER];
    float  rv[ITER];
    float4 v[ITER];

    // Phase 1: index + rho loads (L1-broadcast within 16-lane groups)
    #pragma unroll
    for (int i = 0; i < ITER; i++) {
        unsigned slot = base + i * TPB;
        unsigned e = slot >> 4;
        ok[i] = slot < total;
        r[i]  = ok[i] ? __ldg(&row[e]) : 0;
        rv[i] = ok[i] ? __ldg(&rho[e]) : 0.0f;
    }

    // Phase 2: dependent gathers — 4 independent chains in flight
    #pragma unroll
    for (int i = 0; i < ITER; i++) {
        unsigned sub = (base + i * TPB) & 15u;
        v[i] = __ldg(reinterpret_cast<const float4*>(x)
                     + ((unsigned)r[i] * 16u + sub));
    }

    // Phase 3: rotate + streaming store
    #pragma unroll
    for (int i = 0; i < ITER; i++) {
        if (!ok[i]) continue;
        float s, c;
        __sincosf(rv[i], &s, &c);
        float4 o;
        o.x = fmaf(c, v[i].x, -s * v[i].y);
        o.y = fmaf(s, v[i].x,  c * v[i].y);
        o.z = fmaf(c, v[i].z, -s * v[i].w);
        o.w = fmaf(s, v[i].z,  c * v[i].w);
        __stcs(&out[base + i * TPB], o);
    }
}

extern "C" void kernel_launch(void* const* d_in, const int* in_sizes, int n_in,
                              void* d_out, int out_size)
{
    const float* x    = (const float*)d_in[0];
    const int*   eidx = (const int*)d_in[1];   // (2, E): first E entries = row
    const float* rho  = (const float*)d_in[2];

    unsigned E = (unsigned)in_sizes[2];
    unsigned total = E * 16u;                  // float4 slots

    unsigned per_block = TPB * ITER;
    unsigned blocks = (total + per_block - 1) / per_block;

    pt_kernel<<<blocks, TPB>>>(x, eidx, rho, (float4*)d_out, total);
}

// round 15
// speedup vs baseline: 1.5227x; 1.5227x over previous
#include <cuda_runtime.h>
#include <stdint.h>

// ParallelTransport: out[e, c, :] = R(rho[e]) @ x[row[e], c, :]
// x: (1, N, 32, 2) fp32 ; edge_index: (2, E) int32 ; rho: (E,) fp32
// out: (1, E, 32, 2) fp32
//
// R15: R10 gather/store structure + smem-staged idx/rho.
// Each block covers 64 edges = 1024 float4 slots. Threads 0..63 load the
// block's 64 idx + 64 rho coalesced (4 L1 wavefronts per BLOCK, replacing
// 8 broadcast LDG wavefronts per WARP in R10 — R14 showed L1tex as the
// binding stage on some nodes). Per-slot access is then an LDS broadcast.
// Gathers: 4 independent float4 chains (MLP=4, x is L2-resident 12.8 MB).
// Stores: __stcs streaming (measured best in R12 A/B).

#define ITER 4
#define TPB  256
#define EDGES_PER_BLK 64   /* TPB*ITER/16 */

__global__ void __launch_bounds__(TPB)
pt_kernel(const float* __restrict__ x,
          const int* __restrict__ row,
          const float* __restrict__ rho,
          float4* __restrict__ out,
          unsigned E,
          unsigned total /* E * 16 float4 slots, < 2^31 */)
{
    __shared__ int   s_idx[EDGES_PER_BLK];
    __shared__ float s_rho[EDGES_PER_BLK];

    unsigned t = threadIdx.x;
    unsigned blockEdge0 = blockIdx.x * EDGES_PER_BLK;

    // Stage this block's 64 idx + 64 rho, coalesced.
    if (t < EDGES_PER_BLK) {
        unsigned e = blockEdge0 + t;
        bool ok = e < E;
        s_idx[t] = ok ? __ldg(&row[e]) : 0;
        s_rho[t] = ok ? __ldg(&rho[e]) : 0.0f;
    }
    __syncthreads();

    unsigned base = blockIdx.x * (TPB * ITER) + t;
    unsigned sub  = t & 15u;
    unsigned le0  = t >> 4;            // local edge for i=0; +16 per phase slot

    int    r[ITER];
    float  rv[ITER];
    float4 v[ITER];

    // Phase 1: per-slot idx/rho from smem (broadcast, no L1tex traffic)
    #pragma unroll
    for (int i = 0; i < ITER; i++) {
        unsigned le = le0 + i * (TPB / 16);
        r[i]  = s_idx[le];
        rv[i] = s_rho[le];
    }

    // Phase 2: dependent gathers — 4 independent chains in flight
    #pragma unroll
    for (int i = 0; i < ITER; i++) {
        v[i] = __ldg(reinterpret_cast<const float4*>(x)
                     + ((unsigned)r[i] * 16u + sub));
    }

    // Phase 3: rotate + streaming store
    #pragma unroll
    for (int i = 0; i < ITER; i++) {
        unsigned slot = base + i * TPB;
        if (slot >= total) continue;
        float s, c;
        __sincosf(rv[i], &s, &c);
        float4 o;
        o.x = fmaf(c, v[i].x, -s * v[i].y);
        o.y = fmaf(s, v[i].x,  c * v[i].y);
        o.z = fmaf(c, v[i].z, -s * v[i].w);
        o.w = fmaf(s, v[i].z,  c * v[i].w);
        __stcs(&out[slot], o);
    }
}

extern "C" void kernel_launch(void* const* d_in, const int* in_sizes, int n_in,
                              void* d_out, int out_size)
{
    const float* x    = (const float*)d_in[0];
    const int*   eidx = (const int*)d_in[1];   // (2, E): first E entries = row
    const float* rho  = (const float*)d_in[2];

    unsigned E = (unsigned)in_sizes[2];
    unsigned total = E * 16u;                  // float4 slots

    unsigned per_block = TPB * ITER;           // 1024 slots = 64 edges
    unsigned blocks = (total + per_block - 1) / per_block;

    pt_kernel<<<blocks, TPB>>>(x, eidx, rho, (float4*)d_out, E, total);
}